// round 14
// baseline (speedup 1.0000x reference)
#include <cuda_runtime.h>
#include <cstdint>

#define D      1024
#define LSEQ   2048
#define BATCH  2
#define NH     16
#define DH     64
#define MTOT   (BATCH*LSEQ)

// Scratch (allocation-free rule: __device__ globals)
__device__ float g_q [MTOT*D];
__device__ float g_k [MTOT*D];
__device__ float g_v [MTOT*D];
__device__ float g_ao[MTOT*D];
__device__ float g_xr[MTOT*D];     // tf32-rounded x
__device__ float g_wr[4][D*D];     // tf32-rounded Wq, Wk, Wv, Wo

__device__ __forceinline__ uint32_t smem_u32(const void* p) {
    uint32_t a;
    asm("{ .reg .u64 t; cvta.to.shared.u64 t, %1; cvt.u32.u64 %0, t; }" : "=r"(a) : "l"(p));
    return a;
}
__device__ __forceinline__ uint32_t cvt_tf32(float f) {
    uint32_t o;
    asm("cvt.rna.tf32.f32 %0, %1;" : "=r"(o) : "f"(f));
    return o;
}
__device__ __forceinline__ float cvtf(float f) {
    return __uint_as_float(cvt_tf32(f));
}
__device__ __forceinline__ void cpa16(uint32_t dst, const float* src) {
    asm volatile("cp.async.cg.shared.global [%0], [%1], 16;" :: "r"(dst), "l"(src) : "memory");
}
#define CPA_COMMIT() asm volatile("cp.async.commit_group;" ::: "memory")
#define CPA_WAIT1()  asm volatile("cp.async.wait_group 1;" ::: "memory")
#define CPA_WAIT0()  asm volatile("cp.async.wait_group 0;" ::: "memory")

__device__ __forceinline__ void mma_tf32(float* c,
                                         uint32_t a0, uint32_t a1, uint32_t a2, uint32_t a3,
                                         uint32_t b0, uint32_t b1) {
    asm volatile(
        "mma.sync.aligned.m16n8k8.row.col.f32.tf32.tf32.f32 "
        "{%0,%1,%2,%3}, {%4,%5,%6,%7}, {%8,%9}, {%0,%1,%2,%3};\n"
        : "+f"(c[0]), "+f"(c[1]), "+f"(c[2]), "+f"(c[3])
        : "r"(a0), "r"(a1), "r"(a2), "r"(a3), "r"(b0), "r"(b1));
}

// ===========================================================================
// Prepass: round fp32 -> tf32-rna bit pattern (elementwise, float4).
// blockIdx.y: 0 = x, 1..4 = Wq,Wk,Wv,Wo
// ===========================================================================
__global__ void __launch_bounds__(256) round_kernel(const float* __restrict__ x,
                                                    const float* __restrict__ Wq,
                                                    const float* __restrict__ Wk,
                                                    const float* __restrict__ Wv,
                                                    const float* __restrict__ Wo)
{
    const int z = blockIdx.y;
    const float* s;
    float* d;
    int n4;
    if (z == 0) { s = x; d = g_xr; n4 = MTOT * D / 4; }
    else {
        s = (z == 1) ? Wq : (z == 2) ? Wk : (z == 3) ? Wv : Wo;
        d = g_wr[z - 1];
        n4 = D * D / 4;
    }
    for (int i = blockIdx.x * blockDim.x + threadIdx.x; i < n4;
         i += gridDim.x * blockDim.x) {
        float4 v = ((const float4*)s)[i];
        v.x = cvtf(v.x);
        v.y = cvtf(v.y);
        v.z = cvtf(v.z);
        v.w = cvtf(v.w);
        ((float4*)d)[i] = v;
    }
}

// ===========================================================================
// TF32 mma.sync GEMM: C[M,1024] = A[M,1024] * W[1024,1024]^T (+bias)
// (unchanged from R9: cp.async 3-stage, 128x128 tile, 2 CTAs/SM)
// ===========================================================================
#define PITCH 36
#define TSZF  (128 * PITCH)
#define STGF  (2 * TSZF)
#define GEMM_SMEM (3 * STGF * 4)

__device__ __forceinline__ void gemm_body(const float* __restrict__ A,
                                          const float* __restrict__ W,
                                          const float* __restrict__ bias,
                                          float* __restrict__ C,
                                          float* sm)
{
    const int tid = threadIdx.x;
    const int m0 = blockIdx.y * 128;
    const int n0 = blockIdx.x * 128;
    const int wid    = tid >> 5;
    const int lane   = tid & 31;
    const int warp_m = wid & 3;
    const int warp_n = wid >> 2;
    const int g      = lane >> 2;
    const int tig    = lane & 3;

    const uint32_t smb = smem_u32(sm);
    const int r0 = tid >> 3;
    const int c4 = (tid & 7) * 4;
    const float* Ag = A + (size_t)(m0 + r0) * D + c4;
    const float* Bg = W + (size_t)(n0 + r0) * D + c4;
    const uint32_t wA = smb + (uint32_t)(r0 * PITCH + c4) * 4u;
    const uint32_t wB = wA + TSZF * 4u;

    float acc[2][8][4];
#pragma unroll
    for (int mt = 0; mt < 2; mt++)
#pragma unroll
        for (int nt = 0; nt < 8; nt++)
#pragma unroll
            for (int r = 0; r < 4; r++) acc[mt][nt][r] = 0.f;

    const float* a_base = sm + (warp_m * 32 + g) * PITCH + tig;
    const float* b_base = sm + TSZF + (warp_n * 64 + g) * PITCH + tig;

#pragma unroll
    for (int st = 0; st < 2; st++) {
        const uint32_t so = st * (STGF * 4u);
        const int k0 = st * 32;
#pragma unroll
        for (int j = 0; j < 4; j++) {
            cpa16(wA + so + j * (32 * PITCH * 4u), Ag + (size_t)j * 32 * D + k0);
            cpa16(wB + so + j * (32 * PITCH * 4u), Bg + (size_t)j * 32 * D + k0);
        }
        CPA_COMMIT();
    }

    for (int i = 0; i < 32; i++) {
        if (i < 31) CPA_WAIT1(); else CPA_WAIT0();
        __syncthreads();

        if (i + 2 < 32) {
            const int st = (i + 2) % 3;
            const uint32_t so = st * (STGF * 4u);
            const int k0 = (i + 2) * 32;
#pragma unroll
            for (int j = 0; j < 4; j++) {
                cpa16(wA + so + j * (32 * PITCH * 4u), Ag + (size_t)j * 32 * D + k0);
                cpa16(wB + so + j * (32 * PITCH * 4u), Bg + (size_t)j * 32 * D + k0);
            }
            CPA_COMMIT();
        }

        const int stg = i % 3;
        const float* Ab = a_base + stg * STGF;
        const float* Bb = b_base + stg * STGF;

#pragma unroll
        for (int h = 0; h < 2; h++) {
            float af0[2][2], af1[2][2], af2[2][2], af3[2][2];
#pragma unroll
            for (int mt = 0; mt < 2; mt++) {
#pragma unroll
                for (int kk = 0; kk < 2; kk++) {
                    const float* p = Ab + mt * (16 * PITCH) + 8 * (2 * h + kk);
                    af0[mt][kk] = p[0];
                    af1[mt][kk] = p[8 * PITCH];
                    af2[mt][kk] = p[4];
                    af3[mt][kk] = p[8 * PITCH + 4];
                }
            }
#pragma unroll
            for (int ntp = 0; ntp < 4; ntp++) {
                const float* nb = Bb + 2 * ntp * (8 * PITCH);
                float b0[2][2], b1[2][2];
#pragma unroll
                for (int n2 = 0; n2 < 2; n2++) {
#pragma unroll
                    for (int kk = 0; kk < 2; kk++) {
                        const float* p = nb + n2 * (8 * PITCH) + 8 * (2 * h + kk);
                        b0[n2][kk] = p[0];
                        b1[n2][kk] = p[4];
                    }
                }
#pragma unroll
                for (int kk = 0; kk < 2; kk++)
#pragma unroll
                    for (int mt = 0; mt < 2; mt++)
#pragma unroll
                        for (int n2 = 0; n2 < 2; n2++)
                            mma_tf32(acc[mt][2 * ntp + n2],
                                     __float_as_uint(af0[mt][kk]),
                                     __float_as_uint(af1[mt][kk]),
                                     __float_as_uint(af2[mt][kk]),
                                     __float_as_uint(af3[mt][kk]),
                                     __float_as_uint(b0[n2][kk]),
                                     __float_as_uint(b1[n2][kk]));
            }
        }
    }

#pragma unroll
    for (int mt = 0; mt < 2; mt++) {
        int row = m0 + warp_m * 32 + mt * 16 + g;
#pragma unroll
        for (int nt = 0; nt < 8; nt++) {
            int col = n0 + warp_n * 64 + nt * 8 + 2 * tig;
            float bx = 0.f, by = 0.f;
            if (bias) { bx = bias[col]; by = bias[col + 1]; }
            float2 v0 = make_float2(acc[mt][nt][0] + bx, acc[mt][nt][1] + by);
            float2 v1 = make_float2(acc[mt][nt][2] + bx, acc[mt][nt][3] + by);
            *(float2*)(C + (size_t)row * D + col)       = v0;
            *(float2*)(C + (size_t)(row + 8) * D + col) = v1;
        }
    }
}

__global__ void __launch_bounds__(256, 2) gemm_qkv(const float* __restrict__ x,
                                                   float* __restrict__ Cq,
                                                   float* __restrict__ Ck,
                                                   float* __restrict__ Cv)
{
    extern __shared__ float sm[];
    const int z = blockIdx.z;
    const float* W = g_wr[z];
    float*       C = (z == 0) ? Cq : (z == 1) ? Ck : Cv;
    gemm_body(x, W, nullptr, C, sm);
}

__global__ void __launch_bounds__(256, 2) gemm_o(const float* __restrict__ A,
                                                 const float* __restrict__ bias,
                                                 float* __restrict__ C)
{
    extern __shared__ float sm[];
    gemm_body(A, g_wr[3], bias, C, sm);
}

// ===========================================================================
// Banded mma.sync attention.
// CTA = (64-query tile, head, batch), 128 threads / 4 warps.
// Warp w owns query rows [16w, 16w+16). Local keys kl = 0..127 map to
// global qstart-32+kl (zero rows outside [0,LSEQ) — matches zero-padded ref).
// Row i's 64 window slots = local keys [i, i+63]; warp w's band covers score
// columns [16w, 16w+80) = 10 n-tiles of m16n8k8. Softmax warp-local (rows of
// one m-tile live in lanes 4g..4g+3). P staged in per-warp smem, PV = second
// banded mma against transposed V.
// ===========================================================================
#define QSP 68
#define KSP 68
#define VP  132
#define PP  84
#define QS_OFF 0
#define KS_OFF (64*QSP)              // 4352
#define VT_OFF (KS_OFF + 128*KSP)    // 13056
#define PS_OFF (VT_OFF + 64*VP)      // 21504
#define ATTN_SMEM ((PS_OFF + 4*16*PP) * 4)   // 107520 bytes

__global__ void __launch_bounds__(128, 2) attn_mma()
{
    extern __shared__ float sm[];
    float* Qs = sm + QS_OFF;   // [64][68]   queries
    float* Ks = sm + KS_OFF;   // [128][68]  keys (row = kl)
    float* Vt = sm + VT_OFF;   // [64][132]  V transposed: [dh][kl]
    float* Ps = sm + PS_OFF;   // 4 x [16][84] per-warp P scratch

    const int qstart = blockIdx.x * 64;
    const int h      = blockIdx.y;
    const int b      = blockIdx.z;
    const int tid    = threadIdx.x;
    const int w      = tid >> 5;
    const int lane   = tid & 31;
    const int g      = lane >> 2;
    const int tig    = lane & 3;

    // ---- load Q (tf32-rounded) ----
#pragma unroll
    for (int it = 0; it < 8; it++) {
        int idx = tid + it * 128;
        int q  = idx >> 4;
        int d4 = (idx & 15) * 4;
        float4 v = *(const float4*)(g_q + (size_t)(b * LSEQ + qstart + q) * D + h * DH + d4);
        float* dst = Qs + q * QSP + d4;
        dst[0] = cvtf(v.x); dst[1] = cvtf(v.y); dst[2] = cvtf(v.z); dst[3] = cvtf(v.w);
    }
    // ---- load K (zero-fill out of range, tf32-rounded) ----
#pragma unroll
    for (int it = 0; it < 16; it++) {
        int idx = tid + it * 128;
        int kl = idx >> 4;
        int d4 = (idx & 15) * 4;
        int kg = qstart - 32 + kl;
        float4 v = make_float4(0.f, 0.f, 0.f, 0.f);
        if (kg >= 0 && kg < LSEQ)
            v = *(const float4*)(g_k + (size_t)(b * LSEQ + kg) * D + h * DH + d4);
        float* dst = Ks + kl * KSP + d4;
        dst[0] = cvtf(v.x); dst[1] = cvtf(v.y); dst[2] = cvtf(v.z); dst[3] = cvtf(v.w);
    }
    // ---- load V transposed: Vt[dh][kl] ----
#pragma unroll
    for (int it = 0; it < 16; it++) {
        int idx = tid + it * 128;
        int kl = idx >> 4;
        int d4 = (idx & 15) * 4;
        int kg = qstart - 32 + kl;
        float4 v = make_float4(0.f, 0.f, 0.f, 0.f);
        if (kg >= 0 && kg < LSEQ)
            v = *(const float4*)(g_v + (size_t)(b * LSEQ + kg) * D + h * DH + d4);
        Vt[(d4 + 0) * VP + kl] = cvtf(v.x);
        Vt[(d4 + 1) * VP + kl] = cvtf(v.y);
        Vt[(d4 + 2) * VP + kl] = cvtf(v.z);
        Vt[(d4 + 3) * VP + kl] = cvtf(v.w);
    }
    __syncthreads();

    // ---- S = Q K^T over the band: 10 n-tiles, 8 k-steps ----
    float s[10][4];
#pragma unroll
    for (int t = 0; t < 10; t++)
#pragma unroll
        for (int r = 0; r < 4; r++) s[t][r] = 0.f;

    const float* qb = Qs + (16 * w + g) * QSP + tig;
    const float* kb = Ks + (16 * w + g) * KSP + tig;
#pragma unroll
    for (int kt = 0; kt < 8; kt++) {
        const int k0 = kt * 8;
        uint32_t a0 = __float_as_uint(qb[k0]);
        uint32_t a1 = __float_as_uint(qb[8 * QSP + k0]);
        uint32_t a2 = __float_as_uint(qb[k0 + 4]);
        uint32_t a3 = __float_as_uint(qb[8 * QSP + k0 + 4]);
#pragma unroll
        for (int t = 0; t < 10; t++) {
            const float* kp = kb + t * (8 * KSP) + k0;
            mma_tf32(s[t], a0, a1, a2, a3,
                     __float_as_uint(kp[0]), __float_as_uint(kp[4]));
        }
    }

    // ---- scale + band mask + warp-local softmax ----
    // element (t, e, rh): rel col c = t*8 + 2*tig + e, rel row = g + 8*rh;
    // valid window slot iff 0 <= c - row <= 63.
    float mx0 = -1e30f, mx1 = -1e30f;
#pragma unroll
    for (int t = 0; t < 10; t++) {
#pragma unroll
        for (int e = 0; e < 2; e++) {
            int c  = t * 8 + 2 * tig + e;
            int d0 = c - g;
            int d1 = d0 - 8;
            s[t][e]     = (d0 >= 0 && d0 < 64) ? s[t][e]     * 0.125f : -1e30f;
            s[t][2 + e] = (d1 >= 0 && d1 < 64) ? s[t][2 + e] * 0.125f : -1e30f;
            mx0 = fmaxf(mx0, s[t][e]);
            mx1 = fmaxf(mx1, s[t][2 + e]);
        }
    }
    mx0 = fmaxf(mx0, __shfl_xor_sync(0xffffffffu, mx0, 1));
    mx0 = fmaxf(mx0, __shfl_xor_sync(0xffffffffu, mx0, 2));
    mx1 = fmaxf(mx1, __shfl_xor_sync(0xffffffffu, mx1, 1));
    mx1 = fmaxf(mx1, __shfl_xor_sync(0xffffffffu, mx1, 2));

    float sum0 = 0.f, sum1 = 0.f;
#pragma unroll
    for (int t = 0; t < 10; t++) {
        s[t][0] = __expf(s[t][0] - mx0); sum0 += s[t][0];
        s[t][1] = __expf(s[t][1] - mx0); sum0 += s[t][1];
        s[t][2] = __expf(s[t][2] - mx1); sum1 += s[t][2];
        s[t][3] = __expf(s[t][3] - mx1); sum1 += s[t][3];
    }
    sum0 += __shfl_xor_sync(0xffffffffu, sum0, 1);
    sum0 += __shfl_xor_sync(0xffffffffu, sum0, 2);
    sum1 += __shfl_xor_sync(0xffffffffu, sum1, 1);
    sum1 += __shfl_xor_sync(0xffffffffu, sum1, 2);
    const float inv0 = 1.f / sum0;
    const float inv1 = 1.f / sum1;

    // ---- store P (tf32-rounded) to per-warp scratch ----
    float* pw = Ps + w * 16 * PP;
#pragma unroll
    for (int t = 0; t < 10; t++) {
        int c = t * 8 + 2 * tig;
        pw[g * PP + c]           = cvtf(s[t][0] * inv0);
        pw[g * PP + c + 1]       = cvtf(s[t][1] * inv0);
        pw[(g + 8) * PP + c]     = cvtf(s[t][2] * inv1);
        pw[(g + 8) * PP + c + 1] = cvtf(s[t][3] * inv1);
    }
    __syncwarp();

    // ---- O = P V over the band: 8 n-tiles (dh), 10 k-tiles ----
    float o[8][4];
#pragma unroll
    for (int nt = 0; nt < 8; nt++)
#pragma unroll
        for (int r = 0; r < 4; r++) o[nt][r] = 0.f;

    const float* pb = pw + g * PP + tig;
    const float* vb = Vt + g * VP + 16 * w + tig;
#pragma unroll
    for (int kt = 0; kt < 10; kt++) {
        const int k0 = kt * 8;
        uint32_t a0 = __float_as_uint(pb[k0]);
        uint32_t a1 = __float_as_uint(pb[8 * PP + k0]);
        uint32_t a2 = __float_as_uint(pb[k0 + 4]);
        uint32_t a3 = __float_as_uint(pb[8 * PP + k0 + 4]);
#pragma unroll
        for (int nt = 0; nt < 8; nt++) {
            const float* vp = vb + nt * (8 * VP) + k0;
            mma_tf32(o[nt], a0, a1, a2, a3,
                     __float_as_uint(vp[0]), __float_as_uint(vp[4]));
        }
    }

    // ---- epilogue: write tf32-rounded attention output ----
    const int row0 = qstart + 16 * w + g;
#pragma unroll
    for (int nt = 0; nt < 8; nt++) {
        int col = h * DH + nt * 8 + 2 * tig;
        float2 v0 = make_float2(cvtf(o[nt][0]), cvtf(o[nt][1]));
        float2 v1 = make_float2(cvtf(o[nt][2]), cvtf(o[nt][3]));
        *(float2*)(g_ao + (size_t)(b * LSEQ + row0) * D + col)     = v0;
        *(float2*)(g_ao + (size_t)(b * LSEQ + row0 + 8) * D + col) = v1;
    }
}

// ---------------------------------------------------------------------------
extern "C" void kernel_launch(void* const* d_in, const int* in_sizes, int n_in,
                              void* d_out, int out_size)
{
    const float* x  = (const float*)d_in[0];
    const float* Wq = (const float*)d_in[1];
    const float* Wk = (const float*)d_in[2];
    const float* Wv = (const float*)d_in[3];
    const float* Wo = (const float*)d_in[4];
    const float* bo = (const float*)d_in[5];
    float* out = (float*)d_out;

    float *qp, *kp, *vp, *aop, *xrp;
    cudaGetSymbolAddress((void**)&qp,  g_q);
    cudaGetSymbolAddress((void**)&kp,  g_k);
    cudaGetSymbolAddress((void**)&vp,  g_v);
    cudaGetSymbolAddress((void**)&aop, g_ao);
    cudaGetSymbolAddress((void**)&xrp, g_xr);

    cudaFuncSetAttribute(gemm_qkv, cudaFuncAttributeMaxDynamicSharedMemorySize, GEMM_SMEM);
    cudaFuncSetAttribute(gemm_o,   cudaFuncAttributeMaxDynamicSharedMemorySize, GEMM_SMEM);
    cudaFuncSetAttribute(attn_mma, cudaFuncAttributeMaxDynamicSharedMemorySize, ATTN_SMEM);

    round_kernel<<<dim3(512, 5), 256>>>(x, Wq, Wk, Wv, Wo);

    dim3 gqkv(D / 128, MTOT / 128, 3);   // (8, 32, 3)
    gemm_qkv<<<gqkv, 256, GEMM_SMEM>>>(xrp, qp, kp, vp);

    attn_mma<<<dim3(LSEQ / 64, NH, BATCH), 128, ATTN_SMEM>>>();

    dim3 go(D / 128, MTOT / 128);        // (8, 32)
    gemm_o<<<go, 256, GEMM_SMEM>>>(aop, bo, out);
}

// round 15
// speedup vs baseline: 1.2397x; 1.2397x over previous
#include <cuda_runtime.h>
#include <cstdint>

#define D      1024
#define LSEQ   2048
#define BATCH  2
#define NH     16
#define DH     64
#define MTOT   (BATCH*LSEQ)

// Scratch (allocation-free rule: __device__ globals)
__device__ float g_q [MTOT*D];
__device__ float g_k [MTOT*D];
__device__ float g_v [MTOT*D];
__device__ float g_ao[MTOT*D];     // tf32-rounded, k-permuted attention output
__device__ float g_xr[MTOT*D];     // tf32-rounded, k-permuted x
__device__ float g_wr[4][D*D];     // tf32-rounded, k-permuted Wq, Wk, Wv, Wo

// k-permutation within each 32-float block: slot(k) = (k&3)*8 + (k&4?4:0) + (k>>3)
// => thread tig of an mma group finds its 8 fragment values (b0/b1 x 4 k-steps)
//    contiguous at [tig*8 .. tig*8+7], loadable with two lds.128.

__device__ __forceinline__ uint32_t smem_u32(const void* p) {
    uint32_t a;
    asm("{ .reg .u64 t; cvta.to.shared.u64 t, %1; cvt.u32.u64 %0, t; }" : "=r"(a) : "l"(p));
    return a;
}
__device__ __forceinline__ uint32_t cvt_tf32(float f) {
    uint32_t o;
    asm("cvt.rna.tf32.f32 %0, %1;" : "=r"(o) : "f"(f));
    return o;
}
__device__ __forceinline__ float cvtf(float f) {
    return __uint_as_float(cvt_tf32(f));
}
__device__ __forceinline__ void cpa16(uint32_t dst, const float* src) {
    asm volatile("cp.async.cg.shared.global [%0], [%1], 16;" :: "r"(dst), "l"(src) : "memory");
}
#define CPA_COMMIT() asm volatile("cp.async.commit_group;" ::: "memory")
#define CPA_WAIT1()  asm volatile("cp.async.wait_group 1;" ::: "memory")
#define CPA_WAIT0()  asm volatile("cp.async.wait_group 0;" ::: "memory")

__device__ __forceinline__ void mma_tf32(float* c,
                                         uint32_t a0, uint32_t a1, uint32_t a2, uint32_t a3,
                                         uint32_t b0, uint32_t b1) {
    asm volatile(
        "mma.sync.aligned.m16n8k8.row.col.f32.tf32.tf32.f32 "
        "{%0,%1,%2,%3}, {%4,%5,%6,%7}, {%8,%9}, {%0,%1,%2,%3};\n"
        : "+f"(c[0]), "+f"(c[1]), "+f"(c[2]), "+f"(c[3])
        : "r"(a0), "r"(a1), "r"(a2), "r"(a3), "r"(b0), "r"(b1));
}

// ===========================================================================
// Prepass: round fp32 -> tf32 AND k-permute within each 32-float block.
// blockIdx.y: 0 = x, 1..4 = Wq,Wk,Wv,Wo
// ===========================================================================
__global__ void __launch_bounds__(256) round_kernel(const float* __restrict__ x,
                                                    const float* __restrict__ Wq,
                                                    const float* __restrict__ Wk,
                                                    const float* __restrict__ Wv,
                                                    const float* __restrict__ Wo)
{
    const int z = blockIdx.y;
    const float* s;
    float* d;
    int n4;
    if (z == 0) { s = x; d = g_xr; n4 = MTOT * D / 4; }
    else {
        s = (z == 1) ? Wq : (z == 2) ? Wk : (z == 3) ? Wv : Wo;
        d = g_wr[z - 1];
        n4 = D * D / 4;
    }
    for (int i = blockIdx.x * blockDim.x + threadIdx.x; i < n4;
         i += gridDim.x * blockDim.x) {
        float4 v = ((const float4*)s)[i];
        int e0 = i * 4;                       // element index; e0 % 4 == 0
        int c  = e0 & 31;                     // offset within 32-block
        int bb = e0 - c;                      // block base
        int cst = ((c & 4) ? 4 : 0) + (c >> 3);
        d[bb + cst + 0]  = cvtf(v.x);
        d[bb + cst + 8]  = cvtf(v.y);
        d[bb + cst + 16] = cvtf(v.z);
        d[bb + cst + 24] = cvtf(v.w);
    }
}

// ===========================================================================
// TF32 mma.sync GEMM: C[M,1024] = A[M,1024] * W[1024,1024]^T (+bias)
// A and W are tf32-rounded + k-permuted in global. cp.async 3-stage pipeline
// copies permuted rows verbatim; fragments load with conflict-free lds.128.
// CTA tile 128x128, BK=32, 256 threads, 8 warps (warp tile 32x64), 2 CTAs/SM.
// ===========================================================================
#define PITCH 36
#define TSZF  (128 * PITCH)
#define STGF  (2 * TSZF)
#define GEMM_SMEM (3 * STGF * 4)

__device__ __forceinline__ void gemm_body(const float* __restrict__ A,
                                          const float* __restrict__ W,
                                          const float* __restrict__ bias,
                                          float* __restrict__ C,
                                          float* sm)
{
    const int tid = threadIdx.x;
    const int m0 = blockIdx.y * 128;
    const int n0 = blockIdx.x * 128;
    const int wid    = tid >> 5;
    const int lane   = tid & 31;
    const int warp_m = wid & 3;
    const int warp_n = wid >> 2;
    const int g      = lane >> 2;
    const int tig    = lane & 3;

    const uint32_t smb = smem_u32(sm);
    const int r0 = tid >> 3;
    const int c4 = (tid & 7) * 4;
    const float* Ag = A + (size_t)(m0 + r0) * D + c4;
    const float* Bg = W + (size_t)(n0 + r0) * D + c4;
    const uint32_t wA = smb + (uint32_t)(r0 * PITCH + c4) * 4u;
    const uint32_t wB = wA + TSZF * 4u;

    float acc[2][8][4];
#pragma unroll
    for (int mt = 0; mt < 2; mt++)
#pragma unroll
        for (int nt = 0; nt < 8; nt++)
#pragma unroll
            for (int r = 0; r < 4; r++) acc[mt][nt][r] = 0.f;

    const float* a_base = sm + (warp_m * 32 + g) * PITCH + tig * 8;
    const float* b_base = sm + TSZF + (warp_n * 64 + g) * PITCH + tig * 8;

#pragma unroll
    for (int st = 0; st < 2; st++) {
        const uint32_t so = st * (STGF * 4u);
        const int k0 = st * 32;
#pragma unroll
        for (int j = 0; j < 4; j++) {
            cpa16(wA + so + j * (32 * PITCH * 4u), Ag + (size_t)j * 32 * D + k0);
            cpa16(wB + so + j * (32 * PITCH * 4u), Bg + (size_t)j * 32 * D + k0);
        }
        CPA_COMMIT();
    }

    for (int i = 0; i < 32; i++) {
        if (i < 31) CPA_WAIT1(); else CPA_WAIT0();
        __syncthreads();

        if (i + 2 < 32) {
            const int st = (i + 2) % 3;
            const uint32_t so = st * (STGF * 4u);
            const int k0 = (i + 2) * 32;
#pragma unroll
            for (int j = 0; j < 4; j++) {
                cpa16(wA + so + j * (32 * PITCH * 4u), Ag + (size_t)j * 32 * D + k0);
                cpa16(wB + so + j * (32 * PITCH * 4u), Bg + (size_t)j * 32 * D + k0);
            }
            CPA_COMMIT();
        }

        const int stg = i % 3;
        const float* Asb = a_base + stg * STGF;
        const float* Bsb = b_base + stg * STGF;

        // A fragments: 8 lds.128 cover all 4 k-steps for both m-tiles
        uint32_t af[2][4][4];   // [mt][areg][kstep]
#pragma unroll
        for (int mt = 0; mt < 2; mt++) {
            const float* p = Asb + mt * (16 * PITCH);
            float4 t0 = *(const float4*)(p);                  // a0, ks0..3
            float4 t1 = *(const float4*)(p + 4);              // a2
            float4 t2 = *(const float4*)(p + 8 * PITCH);      // a1
            float4 t3 = *(const float4*)(p + 8 * PITCH + 4);  // a3
            af[mt][0][0] = __float_as_uint(t0.x); af[mt][0][1] = __float_as_uint(t0.y);
            af[mt][0][2] = __float_as_uint(t0.z); af[mt][0][3] = __float_as_uint(t0.w);
            af[mt][1][0] = __float_as_uint(t2.x); af[mt][1][1] = __float_as_uint(t2.y);
            af[mt][1][2] = __float_as_uint(t2.z); af[mt][1][3] = __float_as_uint(t2.w);
            af[mt][2][0] = __float_as_uint(t1.x); af[mt][2][1] = __float_as_uint(t1.y);
            af[mt][2][2] = __float_as_uint(t1.z); af[mt][2][3] = __float_as_uint(t1.w);
            af[mt][3][0] = __float_as_uint(t3.x); af[mt][3][1] = __float_as_uint(t3.y);
            af[mt][3][2] = __float_as_uint(t3.z); af[mt][3][3] = __float_as_uint(t3.w);
        }

        // n-tile pairs: 4 lds.128 each; issue order ks->mt->n2 (dep spacing 4)
#pragma unroll
        for (int ntp = 0; ntp < 4; ntp++) {
            const float* nb = Bsb + 2 * ntp * (8 * PITCH);
            float4 u0a = *(const float4*)(nb);
            float4 u1a = *(const float4*)(nb + 4);
            float4 u0b = *(const float4*)(nb + 8 * PITCH);
            float4 u1b = *(const float4*)(nb + 8 * PITCH + 4);
            uint32_t b0[2][4] = {
                { __float_as_uint(u0a.x), __float_as_uint(u0a.y),
                  __float_as_uint(u0a.z), __float_as_uint(u0a.w) },
                { __float_as_uint(u0b.x), __float_as_uint(u0b.y),
                  __float_as_uint(u0b.z), __float_as_uint(u0b.w) } };
            uint32_t b1[2][4] = {
                { __float_as_uint(u1a.x), __float_as_uint(u1a.y),
                  __float_as_uint(u1a.z), __float_as_uint(u1a.w) },
                { __float_as_uint(u1b.x), __float_as_uint(u1b.y),
                  __float_as_uint(u1b.z), __float_as_uint(u1b.w) } };
#pragma unroll
            for (int ks = 0; ks < 4; ks++)
#pragma unroll
                for (int mt = 0; mt < 2; mt++)
#pragma unroll
                    for (int n2 = 0; n2 < 2; n2++)
                        mma_tf32(acc[mt][2 * ntp + n2],
                                 af[mt][0][ks], af[mt][1][ks],
                                 af[mt][2][ks], af[mt][3][ks],
                                 b0[n2][ks], b1[n2][ks]);
        }
    }

    // ---- epilogue (plain layout output) ----
#pragma unroll
    for (int mt = 0; mt < 2; mt++) {
        int row = m0 + warp_m * 32 + mt * 16 + g;
#pragma unroll
        for (int nt = 0; nt < 8; nt++) {
            int col = n0 + warp_n * 64 + nt * 8 + 2 * tig;
            float bx = 0.f, by = 0.f;
            if (bias) { bx = bias[col]; by = bias[col + 1]; }
            float2 v0 = make_float2(acc[mt][nt][0] + bx, acc[mt][nt][1] + by);
            float2 v1 = make_float2(acc[mt][nt][2] + bx, acc[mt][nt][3] + by);
            *(float2*)(C + (size_t)row * D + col)       = v0;
            *(float2*)(C + (size_t)(row + 8) * D + col) = v1;
        }
    }
}

__global__ void __launch_bounds__(256, 2) gemm_qkv(const float* __restrict__ x,
                                                   float* __restrict__ Cq,
                                                   float* __restrict__ Ck,
                                                   float* __restrict__ Cv)
{
    extern __shared__ float sm[];
    const int z = blockIdx.z;
    const float* W = g_wr[z];
    float*       C = (z == 0) ? Cq : (z == 1) ? Ck : Cv;
    gemm_body(x, W, nullptr, C, sm);
}

__global__ void __launch_bounds__(256, 2) gemm_o(const float* __restrict__ A,
                                                 const float* __restrict__ bias,
                                                 float* __restrict__ C)
{
    extern __shared__ float sm[];
    gemm_body(A, g_wr[3], bias, C, sm);
}

// ===========================================================================
// Banded mma.sync attention (as R14), but the epilogue writes g_ao
// tf32-rounded AND k-permuted (gemm_o consumes it as a permuted A operand).
// ===========================================================================
#define QSP 68
#define KSP 68
#define VP  132
#define PP  84
#define QS_OFF 0
#define KS_OFF (64*QSP)
#define VT_OFF (KS_OFF + 128*KSP)
#define PS_OFF (VT_OFF + 64*VP)
#define ATTN_SMEM ((PS_OFF + 4*16*PP) * 4)   // 107520 bytes

__global__ void __launch_bounds__(128, 2) attn_mma()
{
    extern __shared__ float sm[];
    float* Qs = sm + QS_OFF;   // [64][68]
    float* Ks = sm + KS_OFF;   // [128][68]
    float* Vt = sm + VT_OFF;   // [64][132]  V transposed: [dh][kl]
    float* Ps = sm + PS_OFF;   // 4 x [16][84]

    const int qstart = blockIdx.x * 64;
    const int h      = blockIdx.y;
    const int b      = blockIdx.z;
    const int tid    = threadIdx.x;
    const int w      = tid >> 5;
    const int lane   = tid & 31;
    const int g      = lane >> 2;
    const int tig    = lane & 3;

#pragma unroll
    for (int it = 0; it < 8; it++) {
        int idx = tid + it * 128;
        int q  = idx >> 4;
        int d4 = (idx & 15) * 4;
        float4 v = *(const float4*)(g_q + (size_t)(b * LSEQ + qstart + q) * D + h * DH + d4);
        float* dst = Qs + q * QSP + d4;
        dst[0] = cvtf(v.x); dst[1] = cvtf(v.y); dst[2] = cvtf(v.z); dst[3] = cvtf(v.w);
    }
#pragma unroll
    for (int it = 0; it < 16; it++) {
        int idx = tid + it * 128;
        int kl = idx >> 4;
        int d4 = (idx & 15) * 4;
        int kg = qstart - 32 + kl;
        float4 v = make_float4(0.f, 0.f, 0.f, 0.f);
        if (kg >= 0 && kg < LSEQ)
            v = *(const float4*)(g_k + (size_t)(b * LSEQ + kg) * D + h * DH + d4);
        float* dst = Ks + kl * KSP + d4;
        dst[0] = cvtf(v.x); dst[1] = cvtf(v.y); dst[2] = cvtf(v.z); dst[3] = cvtf(v.w);
    }
#pragma unroll
    for (int it = 0; it < 16; it++) {
        int idx = tid + it * 128;
        int kl = idx >> 4;
        int d4 = (idx & 15) * 4;
        int kg = qstart - 32 + kl;
        float4 v = make_float4(0.f, 0.f, 0.f, 0.f);
        if (kg >= 0 && kg < LSEQ)
            v = *(const float4*)(g_v + (size_t)(b * LSEQ + kg) * D + h * DH + d4);
        Vt[(d4 + 0) * VP + kl] = cvtf(v.x);
        Vt[(d4 + 1) * VP + kl] = cvtf(v.y);
        Vt[(d4 + 2) * VP + kl] = cvtf(v.z);
        Vt[(d4 + 3) * VP + kl] = cvtf(v.w);
    }
    __syncthreads();

    // ---- S = Q K^T over the band ----
    float s[10][4];
#pragma unroll
    for (int t = 0; t < 10; t++)
#pragma unroll
        for (int r = 0; r < 4; r++) s[t][r] = 0.f;

    const float* qb = Qs + (16 * w + g) * QSP + tig;
    const float* kb = Ks + (16 * w + g) * KSP + tig;
#pragma unroll
    for (int kt = 0; kt < 8; kt++) {
        const int k0 = kt * 8;
        uint32_t a0 = __float_as_uint(qb[k0]);
        uint32_t a1 = __float_as_uint(qb[8 * QSP + k0]);
        uint32_t a2 = __float_as_uint(qb[k0 + 4]);
        uint32_t a3 = __float_as_uint(qb[8 * QSP + k0 + 4]);
#pragma unroll
        for (int t = 0; t < 10; t++) {
            const float* kp = kb + t * (8 * KSP) + k0;
            mma_tf32(s[t], a0, a1, a2, a3,
                     __float_as_uint(kp[0]), __float_as_uint(kp[4]));
        }
    }

    // ---- scale + band mask + warp-local softmax ----
    float mx0 = -1e30f, mx1 = -1e30f;
#pragma unroll
    for (int t = 0; t < 10; t++) {
#pragma unroll
        for (int e = 0; e < 2; e++) {
            int c  = t * 8 + 2 * tig + e;
            int d0 = c - g;
            int d1 = d0 - 8;
            s[t][e]     = (d0 >= 0 && d0 < 64) ? s[t][e]     * 0.125f : -1e30f;
            s[t][2 + e] = (d1 >= 0 && d1 < 64) ? s[t][2 + e] * 0.125f : -1e30f;
            mx0 = fmaxf(mx0, s[t][e]);
            mx1 = fmaxf(mx1, s[t][2 + e]);
        }
    }
    mx0 = fmaxf(mx0, __shfl_xor_sync(0xffffffffu, mx0, 1));
    mx0 = fmaxf(mx0, __shfl_xor_sync(0xffffffffu, mx0, 2));
    mx1 = fmaxf(mx1, __shfl_xor_sync(0xffffffffu, mx1, 1));
    mx1 = fmaxf(mx1, __shfl_xor_sync(0xffffffffu, mx1, 2));

    float sum0 = 0.f, sum1 = 0.f;
#pragma unroll
    for (int t = 0; t < 10; t++) {
        s[t][0] = __expf(s[t][0] - mx0); sum0 += s[t][0];
        s[t][1] = __expf(s[t][1] - mx0); sum0 += s[t][1];
        s[t][2] = __expf(s[t][2] - mx1); sum1 += s[t][2];
        s[t][3] = __expf(s[t][3] - mx1); sum1 += s[t][3];
    }
    sum0 += __shfl_xor_sync(0xffffffffu, sum0, 1);
    sum0 += __shfl_xor_sync(0xffffffffu, sum0, 2);
    sum1 += __shfl_xor_sync(0xffffffffu, sum1, 1);
    sum1 += __shfl_xor_sync(0xffffffffu, sum1, 2);
    const float inv0 = 1.f / sum0;
    const float inv1 = 1.f / sum1;

    // ---- store P (tf32-rounded) to per-warp scratch ----
    float* pw = Ps + w * 16 * PP;
#pragma unroll
    for (int t = 0; t < 10; t++) {
        int c = t * 8 + 2 * tig;
        pw[g * PP + c]           = cvtf(s[t][0] * inv0);
        pw[g * PP + c + 1]       = cvtf(s[t][1] * inv0);
        pw[(g + 8) * PP + c]     = cvtf(s[t][2] * inv1);
        pw[(g + 8) * PP + c + 1] = cvtf(s[t][3] * inv1);
    }
    __syncwarp();

    // ---- O = P V over the band ----
    float o[8][4];
#pragma unroll
    for (int nt = 0; nt < 8; nt++)
#pragma unroll
        for (int r = 0; r < 4; r++) o[nt][r] = 0.f;

    const float* pb = pw + g * PP + tig;
    const float* vb = Vt + g * VP + 16 * w + tig;
#pragma unroll
    for (int kt = 0; kt < 10; kt++) {
        const int k0 = kt * 8;
        uint32_t a0 = __float_as_uint(pb[k0]);
        uint32_t a1 = __float_as_uint(pb[8 * PP + k0]);
        uint32_t a2 = __float_as_uint(pb[k0 + 4]);
        uint32_t a3 = __float_as_uint(pb[8 * PP + k0 + 4]);
#pragma unroll
        for (int nt = 0; nt < 8; nt++) {
            const float* vp = vb + nt * (8 * VP) + k0;
            mma_tf32(o[nt], a0, a1, a2, a3,
                     __float_as_uint(vp[0]), __float_as_uint(vp[4]));
        }
    }

    // ---- epilogue: write tf32-rounded, k-PERMUTED attention output ----
    // logical col = h*64 + nt*8 + 2*tig + e; within its 32-block kk = (nt&3)*8 + 2*tig + e
    // slot = (kk&3)*8 + (kk&4?4:0) + (kk>>3), kk>>3 = nt&3
    const int row0 = qstart + 16 * w + g;
    const size_t base0 = (size_t)(b * LSEQ + row0) * D + h * DH;
    const size_t base1 = base0 + 8 * (size_t)D;
#pragma unroll
    for (int nt = 0; nt < 8; nt++) {
        const int blk = (nt & 4) ? 32 : 0;
        const int r3  = nt & 3;
#pragma unroll
        for (int e = 0; e < 2; e++) {
            int q2 = 2 * tig + e;
            int slot = (q2 & 3) * 8 + ((q2 & 4) ? 4 : 0) + r3;
            g_ao[base0 + blk + slot] = cvtf(o[nt][e]);
            g_ao[base1 + blk + slot] = cvtf(o[nt][2 + e]);
        }
    }
}

// ---------------------------------------------------------------------------
extern "C" void kernel_launch(void* const* d_in, const int* in_sizes, int n_in,
                              void* d_out, int out_size)
{
    const float* x  = (const float*)d_in[0];
    const float* Wq = (const float*)d_in[1];
    const float* Wk = (const float*)d_in[2];
    const float* Wv = (const float*)d_in[3];
    const float* Wo = (const float*)d_in[4];
    const float* bo = (const float*)d_in[5];
    float* out = (float*)d_out;

    float *qp, *kp, *vp, *aop, *xrp;
    cudaGetSymbolAddress((void**)&qp,  g_q);
    cudaGetSymbolAddress((void**)&kp,  g_k);
    cudaGetSymbolAddress((void**)&vp,  g_v);
    cudaGetSymbolAddress((void**)&aop, g_ao);
    cudaGetSymbolAddress((void**)&xrp, g_xr);

    cudaFuncSetAttribute(gemm_qkv, cudaFuncAttributeMaxDynamicSharedMemorySize, GEMM_SMEM);
    cudaFuncSetAttribute(gemm_o,   cudaFuncAttributeMaxDynamicSharedMemorySize, GEMM_SMEM);
    cudaFuncSetAttribute(attn_mma, cudaFuncAttributeMaxDynamicSharedMemorySize, ATTN_SMEM);

    round_kernel<<<dim3(512, 5), 256>>>(x, Wq, Wk, Wv, Wo);

    dim3 gqkv(D / 128, MTOT / 128, 3);   // (8, 32, 3)
    gemm_qkv<<<gqkv, 256, GEMM_SMEM>>>(xrp, qp, kp, vp);

    attn_mma<<<dim3(LSEQ / 64, NH, BATCH), 128, ATTN_SMEM>>>();

    dim3 go(D / 128, MTOT / 128);        // (8, 32)
    gemm_o<<<go, 256, GEMM_SMEM>>>(aop, bo, out);
}